// round 2
// baseline (speedup 1.0000x reference)
#include <cuda_runtime.h>
#include <cuda_bf16.h>
#include <math.h>

// ---------------------------------------------------------------------------
// CriticRNN: T=128, B=128, OBS=512, H=1024
//   emb    = relu(WS @ W_emb + b_emb)               [T*B, H]
//   xi     = emb @ Wi + bi                          [T*B, 3H]
//   scan t: h = done? 0 : h;  hh = h @ Wh
//           r = sig(xr+hr); z = sig(xz+hz); n = tanh(xn + r*(hn+bhn))
//           h = (1-z)*n + z*h ; y[t]=h
//   critic = relu(y @ W1 + b1); value = critic @ W2 + b2
// Outputs: h_out = y[T-1]  [B,H]  then value [T,B]
// ---------------------------------------------------------------------------

#define TT  128
#define BB  128
#define OBS 512
#define HH  1024
#define H3  3072
#define MM  (TT * BB)   // 16384

// Static device scratch (no allocations allowed)
__device__ float g_emb[(size_t)MM * HH];      // 64 MB
__device__ float g_xi[(size_t)MM * H3];       // 192 MB
__device__ float g_y[(size_t)MM * HH];        // 64 MB
__device__ float g_critic[(size_t)MM * HH];   // 64 MB
__device__ float g_mask[MM];                  // keep-mask: 1.0 = keep, 0.0 = reset
__device__ int   g_bytemode;

// ---------------------------------------------------------------------------
// dones layout detection + mask expansion.
// If dones is byte-packed bool, reading it as int32 yields values with
// multiple 0/1 bytes (e.g. 257, 65536, ...). If it is int32, every word is
// 0 or 1. Reading the first 4096 words (16 KB) is in-bounds in both layouts.
// ---------------------------------------------------------------------------
__global__ void detect_mask_mode(const unsigned int* __restrict__ d)
{
    __shared__ int flag;
    if (threadIdx.x == 0) flag = 0;
    __syncthreads();
    int f = 0;
    for (int i = threadIdx.x; i < MM / 4; i += blockDim.x)
        if (d[i] > 1u) f = 1;
    if (f) atomicOr(&flag, 1);
    __syncthreads();
    if (threadIdx.x == 0) g_bytemode = flag;
}

__global__ void expand_mask(const void* __restrict__ dones, float* __restrict__ mask)
{
    const int i = blockIdx.x * blockDim.x + threadIdx.x;
    if (i >= MM) return;
    int done;
    if (g_bytemode)
        done = ((const unsigned char*)dones)[i] != 0;
    else
        done = ((const int*)dones)[i] != 0;
    mask[i] = done ? 0.f : 1.f;
}

// ---------------------------------------------------------------------------
// Generic fp32 SGEMM: C[M,N] = op(A[M,K] @ B[K,N] + bias[N])
// BM=BN=128, BK=8, 256 threads, 8x8 per thread. M%128==0, N%128==0, K%8==0.
// ---------------------------------------------------------------------------
template <int DO_RELU>
__global__ __launch_bounds__(256, 2)
void sgemm128(const float* __restrict__ A, const float* __restrict__ B,
              const float* __restrict__ bias, float* __restrict__ C,
              int M, int N, int K)
{
    __shared__ float As[8][128];
    __shared__ float Bs[8][128];

    const int tid  = threadIdx.x;
    const int cRow = blockIdx.y * 128;
    const int cCol = blockIdx.x * 128;

    const int rowA = tid >> 1;          // 0..127
    const int colA = (tid & 1) << 2;    // 0 or 4
    const int rowB = tid >> 5;          // 0..7
    const int colB = (tid & 31) << 2;   // 0..124

    const int tx = tid & 15;            // col group (8 cols)
    const int ty = tid >> 4;            // row group (8 rows)

    float acc[8][8];
    #pragma unroll
    for (int i = 0; i < 8; i++)
        #pragma unroll
        for (int j = 0; j < 8; j++) acc[i][j] = 0.f;

    const float* Ap = A + (size_t)(cRow + rowA) * K + colA;
    const float* Bp = B + cCol + colB + (size_t)rowB * N;

    for (int kb = 0; kb < K; kb += 8) {
        float4 a4 = *(const float4*)(Ap + kb);
        As[colA + 0][rowA] = a4.x;
        As[colA + 1][rowA] = a4.y;
        As[colA + 2][rowA] = a4.z;
        As[colA + 3][rowA] = a4.w;
        float4 b4 = *(const float4*)(Bp + (size_t)kb * N);
        *(float4*)&Bs[rowB][colB] = b4;
        __syncthreads();

        #pragma unroll
        for (int k = 0; k < 8; k++) {
            float regM[8], regN[8];
            *(float4*)&regM[0] = *(const float4*)&As[k][ty * 8];
            *(float4*)&regM[4] = *(const float4*)&As[k][ty * 8 + 4];
            *(float4*)&regN[0] = *(const float4*)&Bs[k][tx * 8];
            *(float4*)&regN[4] = *(const float4*)&Bs[k][tx * 8 + 4];
            #pragma unroll
            for (int i = 0; i < 8; i++)
                #pragma unroll
                for (int j = 0; j < 8; j++)
                    acc[i][j] += regM[i] * regN[j];
        }
        __syncthreads();
    }

    #pragma unroll
    for (int i = 0; i < 8; i++) {
        const int r = cRow + ty * 8 + i;
        #pragma unroll
        for (int j = 0; j < 8; j += 4) {
            const int c = cCol + tx * 8 + j;
            float4 v;
            v.x = acc[i][j + 0] + bias[c + 0];
            v.y = acc[i][j + 1] + bias[c + 1];
            v.z = acc[i][j + 2] + bias[c + 2];
            v.w = acc[i][j + 3] + bias[c + 3];
            if (DO_RELU) {
                v.x = fmaxf(v.x, 0.f); v.y = fmaxf(v.y, 0.f);
                v.z = fmaxf(v.z, 0.f); v.w = fmaxf(v.w, 0.f);
            }
            *(float4*)&C[(size_t)r * N + c] = v;
        }
    }
}

// ---------------------------------------------------------------------------
// One GRU step: reads prev (= y[t-1] or hidden), writes y[t].
// Grid: (H/32, B/32) = (32, 4), 256 threads. Tile 32(b) x 32(h), BK=32.
// mask_t[b]: 1.0 = keep hidden, 0.0 = reset (done).
// ---------------------------------------------------------------------------
__global__ __launch_bounds__(256, 4)
void gru_step(const float* __restrict__ prev,
              const float* __restrict__ mask_t,           // [B] keep-mask
              const float* __restrict__ xi_t,             // [B, 3H]
              const float* __restrict__ Wh,               // [H, 3H]
              const float* __restrict__ bhn,              // [H]
              float* __restrict__ out)                    // [B, H]
{
    __shared__ float hs[32][33];
    __shared__ float ws[3][32][33];

    const int tid = threadIdx.x;
    const int bn  = blockIdx.x * 32;   // h-column base
    const int bm  = blockIdx.y * 32;   // batch-row base
    const int tx  = tid & 31;          // h column within tile
    const int ty  = tid >> 5;          // 0..7 -> batch rows ty + 8*i

    const int lr = tid >> 3;           // 0..31 row
    const int lc = (tid & 7) << 2;     // 0,4,...,28

    const float dmask = mask_t[bm + lr];

    float accR[4] = {0.f, 0.f, 0.f, 0.f};
    float accZ[4] = {0.f, 0.f, 0.f, 0.f};
    float accN[4] = {0.f, 0.f, 0.f, 0.f};

    const float* hRow = prev + (size_t)(bm + lr) * HH + lc;

    for (int kb = 0; kb < HH; kb += 32) {
        float4 h4 = *(const float4*)(hRow + kb);
        hs[lr][lc + 0] = h4.x * dmask;
        hs[lr][lc + 1] = h4.y * dmask;
        hs[lr][lc + 2] = h4.z * dmask;
        hs[lr][lc + 3] = h4.w * dmask;
        #pragma unroll
        for (int g = 0; g < 3; g++) {
            float4 w4 = *(const float4*)(Wh + (size_t)(kb + lr) * H3 + g * HH + bn + lc);
            ws[g][lr][lc + 0] = w4.x;
            ws[g][lr][lc + 1] = w4.y;
            ws[g][lr][lc + 2] = w4.z;
            ws[g][lr][lc + 3] = w4.w;
        }
        __syncthreads();

        #pragma unroll
        for (int k = 0; k < 32; k++) {
            const float wr = ws[0][k][tx];
            const float wz = ws[1][k][tx];
            const float wn = ws[2][k][tx];
            #pragma unroll
            for (int i = 0; i < 4; i++) {
                const float hv = hs[ty + 8 * i][k];
                accR[i] = fmaf(hv, wr, accR[i]);
                accZ[i] = fmaf(hv, wz, accZ[i]);
                accN[i] = fmaf(hv, wn, accN[i]);
            }
        }
        __syncthreads();
    }

    const int j = bn + tx;
    const float bhn_j = bhn[j];
    #pragma unroll
    for (int i = 0; i < 4; i++) {
        const int b = bm + ty + 8 * i;
        const float hp = prev[(size_t)b * HH + j] * mask_t[b];
        const float xr = xi_t[(size_t)b * H3 + j];
        const float xz = xi_t[(size_t)b * H3 + HH + j];
        const float xn = xi_t[(size_t)b * H3 + 2 * HH + j];
        const float r  = 1.f / (1.f + expf(-(xr + accR[i])));
        const float z  = 1.f / (1.f + expf(-(xz + accZ[i])));
        const float n  = tanhf(xn + r * (accN[i] + bhn_j));
        out[(size_t)b * HH + j] = (1.f - z) * n + z * hp;
    }
}

// ---------------------------------------------------------------------------
// value[m] = sum_j critic[m,j] * W2[j] + b2 ; one block per row m
// ---------------------------------------------------------------------------
__global__ __launch_bounds__(256)
void value_kernel(const float* __restrict__ critic, const float* __restrict__ W2,
                  const float* __restrict__ b2, float* __restrict__ out)
{
    const int m   = blockIdx.x;
    const int tid = threadIdx.x;
    float s = 0.f;
    const float* row = critic + (size_t)m * HH;
    for (int j = tid * 4; j < HH; j += 256 * 4) {
        float4 c4 = *(const float4*)(row + j);
        float4 w4 = *(const float4*)(W2 + j);
        s += c4.x * w4.x + c4.y * w4.y + c4.z * w4.z + c4.w * w4.w;
    }
    #pragma unroll
    for (int off = 16; off > 0; off >>= 1)
        s += __shfl_down_sync(0xffffffffu, s, off);
    __shared__ float red[8];
    if ((tid & 31) == 0) red[tid >> 5] = s;
    __syncthreads();
    if (tid == 0) {
        float t = 0.f;
        #pragma unroll
        for (int w = 0; w < 8; w++) t += red[w];
        out[m] = t + b2[0];
    }
}

__global__ void copy_hout(const float* __restrict__ src, float* __restrict__ dst)
{
    const int i = (blockIdx.x * blockDim.x + threadIdx.x) * 4;
    *(float4*)&dst[i] = *(const float4*)&src[i];
}

// ---------------------------------------------------------------------------
// Launch
// ---------------------------------------------------------------------------
extern "C" void kernel_launch(void* const* d_in, const int* in_sizes, int n_in,
                              void* d_out, int out_size)
{
    const float* hidden = (const float*)d_in[0];
    const float* ws     = (const float*)d_in[1];          // [T,B,OBS]
    const void*  dones  = (const void*)d_in[2];           // [T,B] bool/int32
    const float* W_emb  = (const float*)d_in[3];
    const float* b_emb  = (const float*)d_in[4];
    const float* Wi     = (const float*)d_in[5];
    const float* bi     = (const float*)d_in[6];
    const float* Wh     = (const float*)d_in[7];
    const float* bhn    = (const float*)d_in[8];
    const float* W1     = (const float*)d_in[9];
    const float* b1     = (const float*)d_in[10];
    const float* W2     = (const float*)d_in[11];
    const float* b2     = (const float*)d_in[12];
    float* out = (float*)d_out;

    float *emb, *xi, *y, *critic, *mask;
    cudaGetSymbolAddress((void**)&emb,    g_emb);
    cudaGetSymbolAddress((void**)&xi,     g_xi);
    cudaGetSymbolAddress((void**)&y,      g_y);
    cudaGetSymbolAddress((void**)&critic, g_critic);
    cudaGetSymbolAddress((void**)&mask,   g_mask);

    // 0) dones layout detection + keep-mask expansion
    detect_mask_mode<<<1, 256>>>((const unsigned int*)dones);
    expand_mask<<<MM / 256, 256>>>(dones, mask);

    // 1) emb = relu(WS @ W_emb + b_emb)   [16384, 1024]
    {
        dim3 grid(HH / 128, MM / 128);
        sgemm128<1><<<grid, 256>>>(ws, W_emb, b_emb, emb, MM, HH, OBS);
    }
    // 2) xi = emb @ Wi + bi               [16384, 3072]
    {
        dim3 grid(H3 / 128, MM / 128);
        sgemm128<0><<<grid, 256>>>(emb, Wi, bi, xi, MM, H3, HH);
    }
    // 3) GRU scan: 128 sequential steps
    {
        dim3 grid(HH / 32, BB / 32);   // (32, 4)
        const float* prev = hidden;
        for (int t = 0; t < TT; t++) {
            gru_step<<<grid, 256>>>(prev, mask + (size_t)t * BB,
                                    xi + (size_t)t * BB * H3, Wh, bhn,
                                    y + (size_t)t * BB * HH);
            prev = y + (size_t)t * BB * HH;
        }
    }
    // 4) critic = relu(y @ W1 + b1)       [16384, 1024]
    {
        dim3 grid(HH / 128, MM / 128);
        sgemm128<1><<<grid, 256>>>(y, W1, b1, critic, MM, HH, HH);
    }
    // 5) value = critic @ W2 + b2  -> out[131072 ..)
    value_kernel<<<MM, 256>>>(critic, W2, b2, out + (size_t)BB * HH);
    // 6) h_out = y[T-1]            -> out[0 .. 131072)
    copy_hout<<<(BB * HH / 4) / 256, 256>>>(y + (size_t)(TT - 1) * BB * HH, out);
}

// round 3
// speedup vs baseline: 1.0577x; 1.0577x over previous
#include <cuda_runtime.h>
#include <cuda_bf16.h>
#include <math.h>

// ---------------------------------------------------------------------------
// CriticRNN: T=128, B=128, OBS=512, H=1024
// ---------------------------------------------------------------------------

#define TT  128
#define BB  128
#define OBS 512
#define HH  1024
#define H3  3072
#define MM  (TT * BB)   // 16384

// Static device scratch (no allocations allowed)
__device__ float g_emb[(size_t)MM * HH];      // 64 MB
__device__ float g_xi[(size_t)MM * H3];       // 192 MB
__device__ float g_y[(size_t)MM * HH];        // 64 MB
__device__ float g_critic[(size_t)MM * HH];   // 64 MB
__device__ float g_mask[MM];                  // keep-mask: 1.0 = keep, 0.0 = reset
__device__ int   g_bytemode;

// ---------------------------------------------------------------------------
// dones layout detection + mask expansion (byte-bool vs int32).
// ---------------------------------------------------------------------------
__global__ void detect_mask_mode(const unsigned int* __restrict__ d)
{
    __shared__ int flag;
    if (threadIdx.x == 0) flag = 0;
    __syncthreads();
    int f = 0;
    for (int i = threadIdx.x; i < MM / 4; i += blockDim.x)
        if (d[i] > 1u) f = 1;
    if (f) atomicOr(&flag, 1);
    __syncthreads();
    if (threadIdx.x == 0) g_bytemode = flag;
}

__global__ void expand_mask(const void* __restrict__ dones, float* __restrict__ mask)
{
    const int i = blockIdx.x * blockDim.x + threadIdx.x;
    if (i >= MM) return;
    int done;
    if (g_bytemode)
        done = ((const unsigned char*)dones)[i] != 0;
    else
        done = ((const int*)dones)[i] != 0;
    mask[i] = done ? 0.f : 1.f;
}

// ---------------------------------------------------------------------------
// fp32 SGEMM, double-buffered smem: C[M,N] = op(A[M,K] @ B[K,N] + bias[N])
// BM=BN=128, BK=8, 256 threads, 8x8 per thread.
// ---------------------------------------------------------------------------
template <int DO_RELU>
__global__ __launch_bounds__(256, 2)
void sgemm128(const float* __restrict__ A, const float* __restrict__ B,
              const float* __restrict__ bias, float* __restrict__ C,
              int M, int N, int K)
{
    __shared__ float As[2][8][128];
    __shared__ float Bs[2][8][128];

    const int tid  = threadIdx.x;
    const int cRow = blockIdx.y * 128;
    const int cCol = blockIdx.x * 128;

    const int rowA = tid >> 1;          // 0..127
    const int colA = (tid & 1) << 2;    // 0 or 4
    const int rowB = tid >> 5;          // 0..7
    const int colB = (tid & 31) << 2;   // 0..124

    const int tx = tid & 15;            // col group (8 cols)
    const int ty = tid >> 4;            // row group (8 rows)

    float acc[8][8];
    #pragma unroll
    for (int i = 0; i < 8; i++)
        #pragma unroll
        for (int j = 0; j < 8; j++) acc[i][j] = 0.f;

    const float* Ap = A + (size_t)(cRow + rowA) * K + colA;
    const float* Bp = B + cCol + colB + (size_t)rowB * N;

    // prologue: load first tile into buffer 0
    float4 a4 = *(const float4*)(Ap);
    float4 b4 = *(const float4*)(Bp);
    As[0][colA + 0][rowA] = a4.x;
    As[0][colA + 1][rowA] = a4.y;
    As[0][colA + 2][rowA] = a4.z;
    As[0][colA + 3][rowA] = a4.w;
    *(float4*)&Bs[0][rowB][colB] = b4;
    __syncthreads();

    int buf = 0;
    for (int kb = 0; kb < K; kb += 8) {
        const bool more = (kb + 8) < K;
        if (more) {
            a4 = *(const float4*)(Ap + kb + 8);
            b4 = *(const float4*)(Bp + (size_t)(kb + 8) * N);
        }

        #pragma unroll
        for (int k = 0; k < 8; k++) {
            float regM[8], regN[8];
            *(float4*)&regM[0] = *(const float4*)&As[buf][k][ty * 8];
            *(float4*)&regM[4] = *(const float4*)&As[buf][k][ty * 8 + 4];
            *(float4*)&regN[0] = *(const float4*)&Bs[buf][k][tx * 8];
            *(float4*)&regN[4] = *(const float4*)&Bs[buf][k][tx * 8 + 4];
            #pragma unroll
            for (int i = 0; i < 8; i++)
                #pragma unroll
                for (int j = 0; j < 8; j++)
                    acc[i][j] += regM[i] * regN[j];
        }

        if (more) {
            const int nb = buf ^ 1;
            As[nb][colA + 0][rowA] = a4.x;
            As[nb][colA + 1][rowA] = a4.y;
            As[nb][colA + 2][rowA] = a4.z;
            As[nb][colA + 3][rowA] = a4.w;
            *(float4*)&Bs[nb][rowB][colB] = b4;
        }
        buf ^= 1;
        __syncthreads();
    }

    #pragma unroll
    for (int i = 0; i < 8; i++) {
        const int r = cRow + ty * 8 + i;
        #pragma unroll
        for (int j = 0; j < 8; j += 4) {
            const int c = cCol + tx * 8 + j;
            float4 v;
            v.x = acc[i][j + 0] + bias[c + 0];
            v.y = acc[i][j + 1] + bias[c + 1];
            v.z = acc[i][j + 2] + bias[c + 2];
            v.w = acc[i][j + 3] + bias[c + 3];
            if (DO_RELU) {
                v.x = fmaxf(v.x, 0.f); v.y = fmaxf(v.y, 0.f);
                v.z = fmaxf(v.z, 0.f); v.w = fmaxf(v.w, 0.f);
            }
            *(float4*)&C[(size_t)r * N + c] = v;
        }
    }
}

// ---------------------------------------------------------------------------
// One GRU step (v2): tile 32 batch-rows x 32 h-cols x 3 gates, 384 threads.
// Thread = 2 rows x 4 cols x 1 gate -> per 4-k chunk: 6 LDS.128 + 32 FFMA.
// Grid: (HH/32, BB/32) = (32, 4) = 128 blocks.
// ---------------------------------------------------------------------------
__global__ __launch_bounds__(384, 1)
void gru_step2(const float* __restrict__ prev,
               const float* __restrict__ mask_t,           // [B] keep-mask
               const float* __restrict__ xi_t,             // [B, 3H]
               const float* __restrict__ Wh,               // [H, 3H]
               const float* __restrict__ bhn,              // [H]
               float* __restrict__ out)                    // [B, H]
{
    __shared__ float hs[32][36];     // [row][k], row stride 144B (16B aligned)
    __shared__ float wsm[32][100];   // [k][g*32+c], row stride 400B (16B aligned)
    __shared__ float es[3][32][32];  // gate partial sums for epilogue

    const int tid = threadIdx.x;
    const int bn  = blockIdx.x * 32;   // h-column base
    const int bm  = blockIdx.y * 32;   // batch-row base

    const int g   = tid / 128;         // gate 0..2
    const int t2  = tid % 128;
    const int r0  = (t2 >> 3) << 1;    // rows r0, r0+1  (0,2,..,30)
    const int c0  = (t2 & 7) << 2;     // cols c0..c0+3  (0,4,..,28)

    // loader mapping (h tile): tids < 256, one float4 each
    const int lr = tid >> 3;           // 0..31 (only valid for tid<256)
    const int lk = (tid & 7) << 2;     // 0..28
    const float dmask = (tid < 256) ? mask_t[bm + lr] : 0.f;
    const float* hRow = (tid < 256) ? (prev + (size_t)(bm + lr) * HH + lk) : prev;

    float acc[2][4];
    #pragma unroll
    for (int i = 0; i < 2; i++)
        #pragma unroll
        for (int j = 0; j < 4; j++) acc[i][j] = 0.f;

    for (int kb = 0; kb < HH; kb += 32) {
        // load h tile: 32 rows x 32 k = 256 float4
        if (tid < 256) {
            float4 h4 = *(const float4*)(hRow + kb);
            hs[lr][lk + 0] = h4.x * dmask;
            hs[lr][lk + 1] = h4.y * dmask;
            hs[lr][lk + 2] = h4.z * dmask;
            hs[lr][lk + 3] = h4.w * dmask;
        }
        // load weight tile: 32 k x 96 cols = 768 float4, 2 per thread
        #pragma unroll
        for (int i = 0; i < 2; i++) {
            const int f  = tid + i * 384;
            const int wk = f / 24;
            const int c4 = f % 24;
            const int wg = c4 >> 3;
            const int wc = (c4 & 7) << 2;
            float4 w4 = *(const float4*)(Wh + (size_t)(kb + wk) * H3 + wg * HH + bn + wc);
            *(float4*)&wsm[wk][wg * 32 + wc] = w4;
        }
        __syncthreads();

        #pragma unroll
        for (int k4 = 0; k4 < 32; k4 += 4) {
            float4 h0 = *(const float4*)&hs[r0][k4];
            float4 h1 = *(const float4*)&hs[r0 + 1][k4];
            float4 w0 = *(const float4*)&wsm[k4 + 0][g * 32 + c0];
            float4 w1 = *(const float4*)&wsm[k4 + 1][g * 32 + c0];
            float4 w2 = *(const float4*)&wsm[k4 + 2][g * 32 + c0];
            float4 w3 = *(const float4*)&wsm[k4 + 3][g * 32 + c0];

            acc[0][0] = fmaf(h0.x, w0.x, acc[0][0]);
            acc[0][1] = fmaf(h0.x, w0.y, acc[0][1]);
            acc[0][2] = fmaf(h0.x, w0.z, acc[0][2]);
            acc[0][3] = fmaf(h0.x, w0.w, acc[0][3]);
            acc[1][0] = fmaf(h1.x, w0.x, acc[1][0]);
            acc[1][1] = fmaf(h1.x, w0.y, acc[1][1]);
            acc[1][2] = fmaf(h1.x, w0.z, acc[1][2]);
            acc[1][3] = fmaf(h1.x, w0.w, acc[1][3]);

            acc[0][0] = fmaf(h0.y, w1.x, acc[0][0]);
            acc[0][1] = fmaf(h0.y, w1.y, acc[0][1]);
            acc[0][2] = fmaf(h0.y, w1.z, acc[0][2]);
            acc[0][3] = fmaf(h0.y, w1.w, acc[0][3]);
            acc[1][0] = fmaf(h1.y, w1.x, acc[1][0]);
            acc[1][1] = fmaf(h1.y, w1.y, acc[1][1]);
            acc[1][2] = fmaf(h1.y, w1.z, acc[1][2]);
            acc[1][3] = fmaf(h1.y, w1.w, acc[1][3]);

            acc[0][0] = fmaf(h0.z, w2.x, acc[0][0]);
            acc[0][1] = fmaf(h0.z, w2.y, acc[0][1]);
            acc[0][2] = fmaf(h0.z, w2.z, acc[0][2]);
            acc[0][3] = fmaf(h0.z, w2.w, acc[0][3]);
            acc[1][0] = fmaf(h1.z, w2.x, acc[1][0]);
            acc[1][1] = fmaf(h1.z, w2.y, acc[1][1]);
            acc[1][2] = fmaf(h1.z, w2.z, acc[1][2]);
            acc[1][3] = fmaf(h1.z, w2.w, acc[1][3]);

            acc[0][0] = fmaf(h0.w, w3.x, acc[0][0]);
            acc[0][1] = fmaf(h0.w, w3.y, acc[0][1]);
            acc[0][2] = fmaf(h0.w, w3.z, acc[0][2]);
            acc[0][3] = fmaf(h0.w, w3.w, acc[0][3]);
            acc[1][0] = fmaf(h1.w, w3.x, acc[1][0]);
            acc[1][1] = fmaf(h1.w, w3.y, acc[1][1]);
            acc[1][2] = fmaf(h1.w, w3.z, acc[1][2]);
            acc[1][3] = fmaf(h1.w, w3.w, acc[1][3]);
        }
        __syncthreads();
    }

    // stash gate sums
    #pragma unroll
    for (int i = 0; i < 2; i++)
        *(float4*)&es[g][r0 + i][c0] = *(float4*)&acc[i][0];
    __syncthreads();

    // epilogue: 1024 outputs over tids < 256 (4 consecutive cols each)
    if (tid < 256) {
        const int b = bm + lr;
        const int j = bn + lk;
        const float mk = mask_t[b];

        float4 aR = *(const float4*)&es[0][lr][lk];
        float4 aZ = *(const float4*)&es[1][lr][lk];
        float4 aN = *(const float4*)&es[2][lr][lk];
        float4 hp = *(const float4*)(prev + (size_t)b * HH + j);
        float4 xr = *(const float4*)(xi_t + (size_t)b * H3 + j);
        float4 xz = *(const float4*)(xi_t + (size_t)b * H3 + HH + j);
        float4 xn = *(const float4*)(xi_t + (size_t)b * H3 + 2 * HH + j);
        float4 bh = *(const float4*)(bhn + j);

        float4 o;
        {
            const float r = 1.f / (1.f + expf(-(xr.x + aR.x)));
            const float z = 1.f / (1.f + expf(-(xz.x + aZ.x)));
            const float n = tanhf(xn.x + r * (aN.x + bh.x));
            o.x = (1.f - z) * n + z * (hp.x * mk);
        }
        {
            const float r = 1.f / (1.f + expf(-(xr.y + aR.y)));
            const float z = 1.f / (1.f + expf(-(xz.y + aZ.y)));
            const float n = tanhf(xn.y + r * (aN.y + bh.y));
            o.y = (1.f - z) * n + z * (hp.y * mk);
        }
        {
            const float r = 1.f / (1.f + expf(-(xr.z + aR.z)));
            const float z = 1.f / (1.f + expf(-(xz.z + aZ.z)));
            const float n = tanhf(xn.z + r * (aN.z + bh.z));
            o.z = (1.f - z) * n + z * (hp.z * mk);
        }
        {
            const float r = 1.f / (1.f + expf(-(xr.w + aR.w)));
            const float z = 1.f / (1.f + expf(-(xz.w + aZ.w)));
            const float n = tanhf(xn.w + r * (aN.w + bh.w));
            o.w = (1.f - z) * n + z * (hp.w * mk);
        }
        *(float4*)(out + (size_t)b * HH + j) = o;
    }
}

// ---------------------------------------------------------------------------
// value[m] = sum_j critic[m,j] * W2[j] + b2 ; one block per row m
// ---------------------------------------------------------------------------
__global__ __launch_bounds__(256)
void value_kernel(const float* __restrict__ critic, const float* __restrict__ W2,
                  const float* __restrict__ b2, float* __restrict__ out)
{
    const int m   = blockIdx.x;
    const int tid = threadIdx.x;
    float s = 0.f;
    const float* row = critic + (size_t)m * HH;
    for (int j = tid * 4; j < HH; j += 256 * 4) {
        float4 c4 = *(const float4*)(row + j);
        float4 w4 = *(const float4*)(W2 + j);
        s += c4.x * w4.x + c4.y * w4.y + c4.z * w4.z + c4.w * w4.w;
    }
    #pragma unroll
    for (int off = 16; off > 0; off >>= 1)
        s += __shfl_down_sync(0xffffffffu, s, off);
    __shared__ float red[8];
    if ((tid & 31) == 0) red[tid >> 5] = s;
    __syncthreads();
    if (tid == 0) {
        float t = 0.f;
        #pragma unroll
        for (int w = 0; w < 8; w++) t += red[w];
        out[m] = t + b2[0];
    }
}

__global__ void copy_hout(const float* __restrict__ src, float* __restrict__ dst)
{
    const int i = (blockIdx.x * blockDim.x + threadIdx.x) * 4;
    *(float4*)&dst[i] = *(const float4*)&src[i];
}

// ---------------------------------------------------------------------------
// Launch
// ---------------------------------------------------------------------------
extern "C" void kernel_launch(void* const* d_in, const int* in_sizes, int n_in,
                              void* d_out, int out_size)
{
    const float* hidden = (const float*)d_in[0];
    const float* ws     = (const float*)d_in[1];          // [T,B,OBS]
    const void*  dones  = (const void*)d_in[2];           // [T,B] bool/int32
    const float* W_emb  = (const float*)d_in[3];
    const float* b_emb  = (const float*)d_in[4];
    const float* Wi     = (const float*)d_in[5];
    const float* bi     = (const float*)d_in[6];
    const float* Wh     = (const float*)d_in[7];
    const float* bhn    = (const float*)d_in[8];
    const float* W1     = (const float*)d_in[9];
    const float* b1     = (const float*)d_in[10];
    const float* W2     = (const float*)d_in[11];
    const float* b2     = (const float*)d_in[12];
    float* out = (float*)d_out;

    float *emb, *xi, *y, *critic, *mask;
    cudaGetSymbolAddress((void**)&emb,    g_emb);
    cudaGetSymbolAddress((void**)&xi,     g_xi);
    cudaGetSymbolAddress((void**)&y,      g_y);
    cudaGetSymbolAddress((void**)&critic, g_critic);
    cudaGetSymbolAddress((void**)&mask,   g_mask);

    // 0) dones layout detection + keep-mask expansion
    detect_mask_mode<<<1, 256>>>((const unsigned int*)dones);
    expand_mask<<<MM / 256, 256>>>(dones, mask);

    // 1) emb = relu(WS @ W_emb + b_emb)   [16384, 1024]
    {
        dim3 grid(HH / 128, MM / 128);
        sgemm128<1><<<grid, 256>>>(ws, W_emb, b_emb, emb, MM, HH, OBS);
    }
    // 2) xi = emb @ Wi + bi               [16384, 3072]
    {
        dim3 grid(H3 / 128, MM / 128);
        sgemm128<0><<<grid, 256>>>(emb, Wi, bi, xi, MM, H3, HH);
    }
    // 3) GRU scan: 128 sequential steps
    {
        dim3 grid(HH / 32, BB / 32);   // (32, 4) = 128 blocks
        const float* prev = hidden;
        for (int t = 0; t < TT; t++) {
            gru_step2<<<grid, 384>>>(prev, mask + (size_t)t * BB,
                                     xi + (size_t)t * BB * H3, Wh, bhn,
                                     y + (size_t)t * BB * HH);
            prev = y + (size_t)t * BB * HH;
        }
    }
    // 4) critic = relu(y @ W1 + b1)       [16384, 1024]
    {
        dim3 grid(HH / 128, MM / 128);
        sgemm128<1><<<grid, 256>>>(y, W1, b1, critic, MM, HH, HH);
    }
    // 5) value = critic @ W2 + b2  -> out[131072 ..)
    value_kernel<<<MM, 256>>>(critic, W2, b2, out + (size_t)BB * HH);
    // 6) h_out = y[T-1]            -> out[0 .. 131072)
    copy_hout<<<(BB * HH / 4) / 256, 256>>>(y + (size_t)(TT - 1) * BB * HH, out);
}